// round 5
// baseline (speedup 1.0000x reference)
#include <cuda_runtime.h>
#include <cstddef>
#include <cstdint>

// ---------------- problem constants ----------------
constexpr int BWIN = 4096;
constexpr int NTOK = 64;
constexpr int CDIM = 256;
constexpr int HEADS = 8;
constexpr int DHEAD = 32;
constexpr int MROWS = BWIN * NTOK;          // 262144
constexpr float SCALE = 0.1767766952966369f; // 32^-0.5

// ---------------- scratch ----------------
__device__ float g_q[BWIN * HEADS * NTOK * DHEAD];
__device__ float g_k[BWIN * HEADS * NTOK * DHEAD];
__device__ float g_v[BWIN * HEADS * NTOK * DHEAD];
__device__ float g_o[MROWS * CDIM];     // permuted tf32 (A of proj GEMM)
__device__ float g_xt[MROWS * CDIM];    // permuted tf32 x
__device__ float g_wt[1024 * CDIM];     // permuted tf32 weights: [0,256)=Wq, [256,768)=Wkv, [768,1024)=Wp

// ---------------- helpers ----------------
__device__ __forceinline__ float to_tf32(float x) {
    unsigned r;
    asm("cvt.rna.tf32.f32 %0, %1;" : "=r"(r) : "f"(x));
    return __uint_as_float(r);
}
__device__ __forceinline__ unsigned f2u(float x) { return __float_as_uint(x); }

__device__ __forceinline__ void mma_tf32(float* c, unsigned a0, unsigned a1,
                                         unsigned a2, unsigned a3,
                                         unsigned b0, unsigned b1) {
    asm volatile(
        "mma.sync.aligned.m16n8k8.row.col.f32.tf32.tf32.f32 "
        "{%0,%1,%2,%3}, {%4,%5,%6,%7}, {%8,%9}, {%0,%1,%2,%3};"
        : "+f"(c[0]), "+f"(c[1]), "+f"(c[2]), "+f"(c[3])
        : "r"(a0), "r"(a1), "r"(a2), "r"(a3), "r"(b0), "r"(b1));
}

__device__ __forceinline__ void cp16(uint32_t dst, const void* src) {
    asm volatile("cp.async.cg.shared.global [%0], [%1], 16;" :: "r"(dst), "l"(src) : "memory");
}
__device__ __forceinline__ void cp_commit() {
    asm volatile("cp.async.commit_group;" ::: "memory");
}
__device__ __forceinline__ void cp_wait2() {
    asm volatile("cp.async.wait_group 2;" ::: "memory");
}

// ---------------- permute + tf32 round ----------------
// dst[row*256 + 16g + 4c + q] = tf32(src[row*256 + 16g + 4q + c])
__global__ void __launch_bounds__(256) permute_tf32(
    const float* __restrict__ src, float* __restrict__ dst, int ngroups)
{
    int g = blockIdx.x * 256 + threadIdx.x;
    if (g >= ngroups) return;
    const float4* s = (const float4*)src + (size_t)g * 4;
    float4 v0 = s[0], v1 = s[1], v2 = s[2], v3 = s[3];
    float4* d = (float4*)dst + (size_t)g * 4;
    d[0] = make_float4(to_tf32(v0.x), to_tf32(v1.x), to_tf32(v2.x), to_tf32(v3.x));
    d[1] = make_float4(to_tf32(v0.y), to_tf32(v1.y), to_tf32(v2.y), to_tf32(v3.y));
    d[2] = make_float4(to_tf32(v0.z), to_tf32(v1.z), to_tf32(v2.z), to_tf32(v3.z));
    d[3] = make_float4(to_tf32(v0.w), to_tf32(v1.w), to_tf32(v2.w), to_tf32(v3.w));
}

// ---------------- TF32 tensor GEMM, cp.async pipelined ----------------
// out[m,c] = A[m,:] . W[c,:] + b[c];  A,W pre-permuted tf32.
// BM=128, BN=64, BK=16, 4 stages; 8 warps (4x2), warp tile 32x32.
// MODE 0: A=g_xt, W rows 0..767 of g_wt; cols->g_q(scaled)/g_k/g_v scatter.
// MODE 1: A=g_o,  W rows 768..1023 of g_wt -> outP.
template <int MODE>
__global__ void __launch_bounds__(256, 2) mma_gemm(
    const float* __restrict__ b0v, const float* __restrict__ b1v,
    float* __restrict__ outP)
{
    constexpr int STAGES = 4;
    __shared__ float4 As4[STAGES][128 * 4];
    __shared__ float4 Bs4[STAGES][64 * 4];

    const float* A = (MODE == 0) ? g_xt : g_o;
    const int c0 = blockIdx.x * 64;                // c-tile fastest -> A cached in L2
    const int m0 = blockIdx.y * 128;
    const float* Wsrc = g_wt + (MODE == 0 ? 0 : 768 * CDIM);

    const int t = threadIdx.x;
    const int wid = t >> 5, lane = t & 31;
    const int wm = wid & 3, wn = wid >> 2;
    const int gid = lane >> 2, tig = lane & 3;
    const int mrow = wm * 32, ncol = wn * 32;

    float c[2][4][4];
#pragma unroll
    for (int mt = 0; mt < 2; mt++)
#pragma unroll
        for (int nt = 0; nt < 4; nt++)
#pragma unroll
            for (int i = 0; i < 4; i++) c[mt][nt][i] = 0.f;

    // ---- cp.async per-thread mapping ----
    const int arow = t >> 2;       // 0..63
    const int ac = t & 3;          // logical chunk
    const int apc  = ac ^ ((arow >> 1) & 3);
    const int arowB = arow + 64;
    const int apcB = ac ^ ((arowB >> 1) & 3);

    const uint32_t dA0 = (uint32_t)__cvta_generic_to_shared(&As4[0][arow * 4 + apc]);
    const uint32_t dA1 = (uint32_t)__cvta_generic_to_shared(&As4[0][arowB * 4 + apcB]);
    const uint32_t dB  = (uint32_t)__cvta_generic_to_shared(&Bs4[0][arow * 4 + apc]);
    constexpr uint32_t ASTRIDE = 128 * 4 * 16;
    constexpr uint32_t BSTRIDE = 64 * 4 * 16;

    const float* srcA0 = A + (size_t)(m0 + arow) * CDIM + ac * 4;
    const float* srcA1 = A + (size_t)(m0 + arow + 64) * CDIM + ac * 4;
    const float* srcB  = Wsrc + (size_t)(c0 + arow) * CDIM + ac * 4;

    auto issue = [&](int kt, int s) {
        cp16(dA0 + s * ASTRIDE, srcA0 + kt * 16);
        cp16(dA1 + s * ASTRIDE, srcA1 + kt * 16);
        cp16(dB  + s * BSTRIDE, srcB  + kt * 16);
    };

    // ---- fragment load indices (float4 units) ----
    int aIdx[2][2], bIdx[4];
#pragma unroll
    for (int mt = 0; mt < 2; mt++) {
        int r0 = mrow + mt * 16 + gid;
        int r1 = r0 + 8;
        aIdx[mt][0] = r0 * 4 + (tig ^ ((r0 >> 1) & 3));
        aIdx[mt][1] = r1 * 4 + (tig ^ ((r1 >> 1) & 3));
    }
#pragma unroll
    for (int nt = 0; nt < 4; nt++) {
        int nb = ncol + nt * 8 + gid;
        bIdx[nt] = nb * 4 + (tig ^ ((nb >> 1) & 3));
    }

    // ---- prologue: stages 0..2 ----
#pragma unroll
    for (int s = 0; s < STAGES - 1; s++) {
        issue(s, s);
        cp_commit();
    }

#pragma unroll
    for (int kt = 0; kt < 16; kt++) {
        const int buf = kt & 3;
        cp_wait2();
        __syncthreads();

        {
            const float4* as = As4[buf];
            const float4* bs = Bs4[buf];
            float4 a4[2][2], b4[4];
#pragma unroll
            for (int mt = 0; mt < 2; mt++) {
                a4[mt][0] = as[aIdx[mt][0]];
                a4[mt][1] = as[aIdx[mt][1]];
            }
#pragma unroll
            for (int nt = 0; nt < 4; nt++) b4[nt] = bs[bIdx[nt]];

#pragma unroll
            for (int mt = 0; mt < 2; mt++)
#pragma unroll
                for (int nt = 0; nt < 4; nt++)
                    mma_tf32(c[mt][nt],
                             f2u(a4[mt][0].x), f2u(a4[mt][1].x),
                             f2u(a4[mt][0].y), f2u(a4[mt][1].y),
                             f2u(b4[nt].x),    f2u(b4[nt].y));
#pragma unroll
            for (int mt = 0; mt < 2; mt++)
#pragma unroll
                for (int nt = 0; nt < 4; nt++)
                    mma_tf32(c[mt][nt],
                             f2u(a4[mt][0].z), f2u(a4[mt][1].z),
                             f2u(a4[mt][0].w), f2u(a4[mt][1].w),
                             f2u(b4[nt].z),    f2u(b4[nt].w));
        }

        if (kt + STAGES - 1 < 16) issue(kt + STAGES - 1, (kt + STAGES - 1) & 3);
        cp_commit();
    }

    // ---------------- epilogue ----------------
#pragma unroll
    for (int mt = 0; mt < 2; mt++) {
#pragma unroll
        for (int nt = 0; nt < 4; nt++) {
            int clocal = ncol + nt * 8 + 2 * tig;
            int cg = c0 + clocal;
            float bias0, bias1;
            if (MODE == 1) { bias0 = b0v[cg]; bias1 = b0v[cg + 1]; }
            else if (cg < 256) { bias0 = b0v[cg]; bias1 = b0v[cg + 1]; }
            else { bias0 = b1v[cg - 256]; bias1 = b1v[cg - 255]; }
#pragma unroll
            for (int rr = 0; rr < 2; rr++) {
                int row = m0 + mrow + mt * 16 + gid + rr * 8;
                float v0 = c[mt][nt][rr * 2 + 0] + bias0;
                float v1 = c[mt][nt][rr * 2 + 1] + bias1;
                if (MODE == 1) {
                    float2* p = (float2*)(outP + (size_t)row * CDIM + cg);
                    *p = make_float2(v0, v1);
                } else {
                    int cc = cg;
                    int b = row >> 6, n = row & 63;
                    float* base;
                    if (cc < 256) { base = g_q; v0 *= SCALE; v1 *= SCALE; }
                    else if (cc < 512) { base = g_k; cc -= 256; }
                    else { base = g_v; cc -= 512; }
                    int hh = cc >> 5, dd = cc & 31;
                    float2* p = (float2*)(base + (((size_t)(b * 8 + hh)) * 64 + n) * 32 + dd);
                    *p = make_float2(v0, v1);
                }
            }
        }
    }
}

// ---------------- fused attention per (window, head) ----------------
__global__ void __launch_bounds__(256) attn_kernel(
    const float* __restrict__ mask,
    const float* __restrict__ bias_table)
{
    const int bh = blockIdx.x;
    const int b  = bh >> 3;
    const int h  = bh & 7;

    __shared__ float qs_t[32 * 64];
    __shared__ float ks_t[32 * 64];
    __shared__ float vs[64 * 32];
    __shared__ float S[64 * 65];
    __shared__ float rowmax[64];
    __shared__ float rowinv[64];

    const int t = threadIdx.x;
    const float* qg = g_q + (size_t)bh * 2048;
    const float* kg = g_k + (size_t)bh * 2048;
    const float* vg = g_v + (size_t)bh * 2048;

#pragma unroll
    for (int it = 0; it < 2; it++) {
        int e = (t + it * 256) * 4;
        int n = e >> 5;
        int d = e & 31;
        float4 vq = *(const float4*)&qg[e];
        float4 vk = *(const float4*)&kg[e];
        float4 vv = *(const float4*)&vg[e];
        qs_t[(d + 0) * 64 + n] = vq.x;
        qs_t[(d + 1) * 64 + n] = vq.y;
        qs_t[(d + 2) * 64 + n] = vq.z;
        qs_t[(d + 3) * 64 + n] = vq.w;
        ks_t[(d + 0) * 64 + n] = vk.x;
        ks_t[(d + 1) * 64 + n] = vk.y;
        ks_t[(d + 2) * 64 + n] = vk.z;
        ks_t[(d + 3) * 64 + n] = vk.w;
        *(float4*)&vs[e] = vv;
    }
    __syncthreads();

    const int i0 = (t >> 4) << 2;
    const int j0 = (t & 15) << 2;
    float s[4][4];
#pragma unroll
    for (int i = 0; i < 4; i++)
#pragma unroll
        for (int j = 0; j < 4; j++) s[i][j] = 0.f;

#pragma unroll
    for (int d = 0; d < 32; d++) {
        float qr[4], kr[4];
        *(float4*)qr = *(const float4*)&qs_t[d * 64 + i0];
        *(float4*)kr = *(const float4*)&ks_t[d * 64 + j0];
#pragma unroll
        for (int i = 0; i < 4; i++)
#pragma unroll
            for (int j = 0; j < 4; j++)
                s[i][j] = fmaf(qr[i], kr[j], s[i][j]);
    }

    const int w = b & 1023;
    const float* mrow = mask + (size_t)w * 4096;
#pragma unroll
    for (int i = 0; i < 4; i++) {
        int ii = i0 + i;
        int ih = ii >> 3, iw = ii & 7;
#pragma unroll
        for (int j = 0; j < 4; j++) {
            int jj = j0 + j;
            int jh = jj >> 3, jw = jj & 7;
            int ridx = (ih - jh + 7) * 15 + (iw - jw + 7);
            S[ii * 65 + jj] = s[i][j] + bias_table[ridx * 8 + h] + mrow[ii * 64 + jj];
        }
    }
    __syncthreads();

    if (t < 64) {
        float mx = S[t * 65];
        for (int j = 1; j < 64; j++) mx = fmaxf(mx, S[t * 65 + j]);
        rowmax[t] = mx;
    }
    __syncthreads();

#pragma unroll
    for (int i = 0; i < 4; i++) {
        float mx = rowmax[i0 + i];
#pragma unroll
        for (int j = 0; j < 4; j++) {
            int idx = (i0 + i) * 65 + (j0 + j);
            S[idx] = __expf(S[idx] - mx);
        }
    }
    __syncthreads();

    if (t < 64) {
        float ssum = 0.f;
        for (int j = 0; j < 64; j++) ssum += S[t * 65 + j];
        rowinv[t] = 1.0f / ssum;
    }
    __syncthreads();

    const int oi = t >> 2;
    const int d0 = (t & 3) << 3;
    float o[8];
#pragma unroll
    for (int dd = 0; dd < 8; dd++) o[dd] = 0.f;

    for (int j = 0; j < 64; j++) {
        float p = S[oi * 65 + j];
        float4 va = *(const float4*)&vs[j * 32 + d0];
        float4 vb = *(const float4*)&vs[j * 32 + d0 + 4];
        o[0] = fmaf(p, va.x, o[0]);
        o[1] = fmaf(p, va.y, o[1]);
        o[2] = fmaf(p, va.z, o[2]);
        o[3] = fmaf(p, va.w, o[3]);
        o[4] = fmaf(p, vb.x, o[4]);
        o[5] = fmaf(p, vb.y, o[5]);
        o[6] = fmaf(p, vb.z, o[6]);
        o[7] = fmaf(p, vb.w, o[7]);
    }
    float inv = rowinv[oi];
    // store permuted + tf32-rounded (A operand of proj GEMM)
    size_t rowoff = ((size_t)(b * 64 + oi)) * CDIM;
    int colbase = h * 32 + d0;
#pragma unroll
    for (int dd = 0; dd < 8; dd++) {
        int col = colbase + dd;
        int p = (col & ~15) | ((col & 3) << 2) | ((col >> 2) & 3);
        g_o[rowoff + p] = to_tf32(o[dd] * inv);
    }
}

// ---------------- launch ----------------
extern "C" void kernel_launch(void* const* d_in, const int* in_sizes, int n_in,
                              void* d_out, int out_size)
{
    const float* x          = (const float*)d_in[0];
    const float* mask       = (const float*)d_in[1];
    const float* Wq         = (const float*)d_in[2];
    const float* bq         = (const float*)d_in[3];
    const float* Wkv        = (const float*)d_in[4];
    const float* bkv        = (const float*)d_in[5];
    const float* bias_table = (const float*)d_in[6];
    const float* Wp         = (const float*)d_in[7];
    const float* bp         = (const float*)d_in[8];
    float* out = (float*)d_out;

    float* wt;
    cudaGetSymbolAddress((void**)&wt, g_wt);
    float* xt;
    cudaGetSymbolAddress((void**)&xt, g_xt);

    // permute + tf32 round operands
    permute_tf32<<<(MROWS * 16 + 255) / 256, 256>>>(x, xt, MROWS * 16);
    permute_tf32<<<(256 * 16 + 255) / 256, 256>>>(Wq, wt, 256 * 16);
    permute_tf32<<<(512 * 16 + 255) / 256, 256>>>(Wkv, wt + 256 * CDIM, 512 * 16);
    permute_tf32<<<(256 * 16 + 255) / 256, 256>>>(Wp, wt + 768 * CDIM, 256 * 16);

    mma_gemm<0><<<dim3(12, MROWS / 128), 256>>>(bq, bkv, nullptr);
    attn_kernel<<<BWIN * HEADS, 256>>>(mask, bias_table);
    mma_gemm<1><<<dim3(4, MROWS / 128), 256>>>(bp, nullptr, out);
}